// round 1
// baseline (speedup 1.0000x reference)
#include <cuda_runtime.h>

#define B_TOK   16384
#define DIM     4096
#define NE      64
#define KC      32
#define BM      64
#define NTHREADS 128
#define NCHUNK  (DIM / KC)

// ---- packed f32x2 helpers (sm_103a FFMA2: 2x fp32 FMA throughput) ----
__device__ __forceinline__ unsigned long long pack_dup(float x) {
    unsigned long long r;
    unsigned u = __float_as_uint(x);
    asm("mov.b64 %0, {%1, %1};" : "=l"(r) : "r"(u));
    return r;
}
__device__ __forceinline__ unsigned long long pack_xy(float x, float y) {
    unsigned long long r;
    asm("mov.b64 %0, {%1, %2};" : "=l"(r)
        : "r"(__float_as_uint(x)), "r"(__float_as_uint(y)));
    return r;
}
__device__ __forceinline__ void ffma2(unsigned long long& d,
                                      unsigned long long a,
                                      unsigned long long b) {
    asm("fma.rn.f32x2 %0, %1, %2, %0;" : "+l"(d) : "l"(a), "l"(b));
}

__global__ void __launch_bounds__(NTHREADS, 2)
mome_gate_kernel(const float* __restrict__ h,
                 const float* __restrict__ w,
                 const float* __restrict__ bias,
                 float* __restrict__ out)
{
    __shared__ float Hs[2][KC][BM];   // 16 KB (== 64x64 floats, reused as logits)
    __shared__ float Ws[2][KC][NE];   // 16 KB

    const int tid = threadIdx.x;
    const int rowBase = blockIdx.x * BM;

    // compute-tile mapping: 4 rows x 8 experts per thread
    const int er = tid & 7;    // expert group -> experts [er*8, er*8+8)
    const int rr = tid >> 3;   // row group    -> rows    [rr*4, rr*4+4)

    // load mapping: each thread owns (row-or-expert lr, k-half lq) = 16 floats
    const int lr = tid & 63;
    const int lq = tid >> 6;

    const float* hp = h + (size_t)(rowBase + lr) * DIM + lq * 16;
    const float* wp = w + (size_t)lr * DIM + lq * 16;

    unsigned long long acc[4][4];  // [row][expert-pair] packed f32x2
#pragma unroll
    for (int i = 0; i < 4; i++)
#pragma unroll
        for (int p = 0; p < 4; p++) acc[i][p] = 0ull;

    float4 hr[4], wr[4];

    // prologue: load + stage chunk 0
#pragma unroll
    for (int i = 0; i < 4; i++) {
        hr[i] = *(const float4*)(hp + i * 4);
        wr[i] = *(const float4*)(wp + i * 4);
    }
#pragma unroll
    for (int i = 0; i < 4; i++) {
        int kk = lq * 16 + i * 4;
        Hs[0][kk + 0][lr] = hr[i].x; Hs[0][kk + 1][lr] = hr[i].y;
        Hs[0][kk + 2][lr] = hr[i].z; Hs[0][kk + 3][lr] = hr[i].w;
        Ws[0][kk + 0][lr] = wr[i].x; Ws[0][kk + 1][lr] = wr[i].y;
        Ws[0][kk + 2][lr] = wr[i].z; Ws[0][kk + 3][lr] = wr[i].w;
    }
    __syncthreads();

    int buf = 0;
    for (int c = 0; c < NCHUNK; c++) {
        // prefetch next chunk into registers while computing current
        if (c + 1 < NCHUNK) {
            const float* hq = hp + (size_t)(c + 1) * KC;
            const float* wq = wp + (size_t)(c + 1) * KC;
#pragma unroll
            for (int i = 0; i < 4; i++) {
                hr[i] = *(const float4*)(hq + i * 4);
                wr[i] = *(const float4*)(wq + i * 4);
            }
        }

#pragma unroll
        for (int k = 0; k < KC; k++) {
            const float4 hv = *(const float4*)&Hs[buf][k][rr * 4];
            unsigned long long hd0 = pack_dup(hv.x);
            unsigned long long hd1 = pack_dup(hv.y);
            unsigned long long hd2 = pack_dup(hv.z);
            unsigned long long hd3 = pack_dup(hv.w);

            const float4 wv0 = *(const float4*)&Ws[buf][k][er * 8];
            const float4 wv1 = *(const float4*)&Ws[buf][k][er * 8 + 4];
            unsigned long long wd0 = pack_xy(wv0.x, wv0.y);
            unsigned long long wd1 = pack_xy(wv0.z, wv0.w);
            unsigned long long wd2 = pack_xy(wv1.x, wv1.y);
            unsigned long long wd3 = pack_xy(wv1.z, wv1.w);

            ffma2(acc[0][0], hd0, wd0); ffma2(acc[0][1], hd0, wd1);
            ffma2(acc[0][2], hd0, wd2); ffma2(acc[0][3], hd0, wd3);
            ffma2(acc[1][0], hd1, wd0); ffma2(acc[1][1], hd1, wd1);
            ffma2(acc[1][2], hd1, wd2); ffma2(acc[1][3], hd1, wd3);
            ffma2(acc[2][0], hd2, wd0); ffma2(acc[2][1], hd2, wd1);
            ffma2(acc[2][2], hd2, wd2); ffma2(acc[2][3], hd2, wd3);
            ffma2(acc[3][0], hd3, wd0); ffma2(acc[3][1], hd3, wd1);
            ffma2(acc[3][2], hd3, wd2); ffma2(acc[3][3], hd3, wd3);
        }

        if (c + 1 < NCHUNK) {
            const int nb = buf ^ 1;
#pragma unroll
            for (int i = 0; i < 4; i++) {
                int kk = lq * 16 + i * 4;
                Hs[nb][kk + 0][lr] = hr[i].x; Hs[nb][kk + 1][lr] = hr[i].y;
                Hs[nb][kk + 2][lr] = hr[i].z; Hs[nb][kk + 3][lr] = hr[i].w;
                Ws[nb][kk + 0][lr] = wr[i].x; Ws[nb][kk + 1][lr] = wr[i].y;
                Ws[nb][kk + 2][lr] = wr[i].z; Ws[nb][kk + 3][lr] = wr[i].w;
            }
            __syncthreads();
            buf = nb;
        }
    }

    // ---- epilogue: logits -> smem, per-row top-2, weights + indices ----
    __syncthreads();
    float* Ls = (float*)Hs;  // 64 rows x 64 experts = 4096 floats (exactly Hs)

#pragma unroll
    for (int i = 0; i < 4; i++) {
        const int row = rr * 4 + i;
#pragma unroll
        for (int p = 0; p < 4; p++) {
            const unsigned long long a = acc[i][p];
            const float lo = __uint_as_float((unsigned)(a & 0xffffffffull));
            const float hi = __uint_as_float((unsigned)(a >> 32));
            const int e0 = er * 8 + p * 2;
            Ls[row * NE + e0]     = lo + bias[e0];
            Ls[row * NE + e0 + 1] = hi + bias[e0 + 1];
        }
    }
    __syncthreads();

    if (tid < BM) {
        const float* lrow = &Ls[tid * NE];
        float v0 = -1e30f, v1 = -1e30f;
        int i0 = 0, i1 = 0;
#pragma unroll
        for (int e = 0; e < NE; e++) {
            const float v = lrow[e];
            if (v > v0)      { v1 = v0; i1 = i0; v0 = v; i0 = e; }
            else if (v > v1) { v1 = v; i1 = e; }
        }
        // softmax Z cancels: w0 = 1/(1+exp(l1-l0)), w1 = exp(l1-l0)/(1+...)
        const float t  = expf(v1 - v0);
        const float w0 = 1.0f / (1.0f + t);
        const float w1 = 1.0f - w0;

        const size_t g = (size_t)rowBase + tid;
        out[2 * g]     = w0;
        out[2 * g + 1] = w1;
        float* oi = out + 2 * (size_t)B_TOK;
        oi[2 * g]     = (float)i0;
        oi[2 * g + 1] = (float)i1;
    }
}

extern "C" void kernel_launch(void* const* d_in, const int* in_sizes, int n_in,
                              void* d_out, int out_size)
{
    const float* h    = (const float*)d_in[0];
    const float* w    = (const float*)d_in[1];
    const float* bias = (const float*)d_in[2];
    float* out        = (float*)d_out;

    mome_gate_kernel<<<B_TOK / BM, NTHREADS>>>(h, w, bias, out);
}

// round 2
// speedup vs baseline: 2.0138x; 2.0138x over previous
#include <cuda_runtime.h>

#define B_TOK   16384
#define DIM     4096
#define NE      64
#define BM      64
#define KC      64
#define NCH     (DIM / KC)   // 64 chunks
#define NT      256

// dynamic smem layout (floats):
//   Hs: [2][BM][KC]  at offset 0      (8192 floats)
//   Ws: [2][NE][KC]  at offset 8192   (8192 floats)
// total 64 KB. Ls (logits 64x66) reuses the Hs region in the epilogue.
#define HS(b, r, f) sm[((b) << 12) + ((r) << 6) + (f)]
#define WS(b, r, f) sm[8192 + ((b) << 12) + ((r) << 6) + (f)]

__device__ __forceinline__ void ffma2(unsigned long long& d,
                                      unsigned long long a,
                                      unsigned long long b) {
    asm("fma.rn.f32x2 %0, %1, %2, %0;" : "+l"(d) : "l"(a), "l"(b));
}
__device__ __forceinline__ void cpa16(void* dst, const void* src) {
    unsigned d = (unsigned)__cvta_generic_to_shared(dst);
    asm volatile("cp.async.cg.shared.global [%0], [%1], 16;" :: "r"(d), "l"(src));
}
__device__ __forceinline__ void cpa_commit() {
    asm volatile("cp.async.commit_group;" ::: "memory");
}
__device__ __forceinline__ void cpa_wait0() {
    asm volatile("cp.async.wait_group 0;" ::: "memory");
}

__global__ void __launch_bounds__(NT, 2)
mome_gate2(const float* __restrict__ h,
           const float* __restrict__ w,
           const float* __restrict__ bias,
           float* __restrict__ out)
{
    extern __shared__ float sm[];

    const int tid = threadIdx.x;
    const int er  = tid & 15;   // experts er*4 .. er*4+3
    const int rr  = tid >> 4;   // rows    rr*4 .. rr*4+3
    const int rowBase = blockIdx.x * BM;

    const float* hG = h + (size_t)rowBase * DIM;
    const float* wG = w;

    // load mapping: idx = j*256 + tid -> (row = idx>>4, 16B-unit u = idx&15)
    const int l_row = tid >> 4;          // j adds 16 rows per step
    const int l_u   = tid & 15;

    unsigned long long acc[4][4];
#pragma unroll
    for (int r = 0; r < 4; r++)
#pragma unroll
        for (int e = 0; e < 4; e++) acc[r][e] = 0ull;

    // ---- async load of chunk c into buffer b (swizzled: phys_u = u ^ (row>>2)) ----
    auto load_chunk = [&](int c, int b) {
#pragma unroll
        for (int j = 0; j < 4; j++) {
            const int row = l_row + j * 16;
            const int su  = l_u ^ ((row >> 2) & 15);
            cpa16(&HS(b, row, su * 4), hG + (size_t)row * DIM + c * KC + l_u * 4);
            cpa16(&WS(b, row, su * 4), wG + (size_t)row * DIM + c * KC + l_u * 4);
        }
        cpa_commit();
    };

    load_chunk(0, 0);

    int buf = 0;
    for (int c = 0; c < NCH; c++) {
        cpa_wait0();
        __syncthreads();
        if (c + 1 < NCH) load_chunk(c + 1, buf ^ 1);

        // ---- compute chunk: k packed into f32x2 lanes ----
#pragma unroll
        for (int k4 = 0; k4 < 16; k4++) {
            const int hu = (k4 ^ rr) << 2;   // h rows rr*4+r -> row>>2 == rr
            const int wu = (k4 ^ er) << 2;   // w rows er*4+e -> row>>2 == er

            ulonglong2 hv[4], wv[4];
#pragma unroll
            for (int r = 0; r < 4; r++)
                hv[r] = *(const ulonglong2*)&HS(buf, rr * 4 + r, hu);
#pragma unroll
            for (int e = 0; e < 4; e++)
                wv[e] = *(const ulonglong2*)&WS(buf, er * 4 + e, wu);

#pragma unroll
            for (int r = 0; r < 4; r++)
#pragma unroll
                for (int e = 0; e < 4; e++) {
                    ffma2(acc[r][e], hv[r].x, wv[e].x);
                    ffma2(acc[r][e], hv[r].y, wv[e].y);
                }
        }
        buf ^= 1;
    }

    // ---- epilogue: combine k-halves, add bias, top-2 per row ----
    __syncthreads();
    float* Ls = sm;              // reuse Hs region: [64][66]

    float bs[4];
#pragma unroll
    for (int e = 0; e < 4; e++) bs[e] = __ldg(&bias[er * 4 + e]);

#pragma unroll
    for (int r = 0; r < 4; r++)
#pragma unroll
        for (int e = 0; e < 4; e++) {
            const unsigned long long a = acc[r][e];
            const float lo = __uint_as_float((unsigned)(a & 0xffffffffull));
            const float hi = __uint_as_float((unsigned)(a >> 32));
            Ls[(rr * 4 + r) * 66 + (er * 4 + e)] = lo + hi + bs[e];
        }
    __syncthreads();

    if (tid < BM) {
        const float* lrow = &Ls[tid * 66];
        float v0 = -1e30f, v1 = -1e30f;
        int i0 = 0, i1 = 0;
#pragma unroll
        for (int e = 0; e < NE; e++) {
            const float v = lrow[e];
            if (v > v0)      { v1 = v0; i1 = i0; v0 = v; i0 = e; }
            else if (v > v1) { v1 = v; i1 = e; }
        }
        const float t  = expf(v1 - v0);
        const float w0 = 1.0f / (1.0f + t);
        const float w1 = 1.0f - w0;

        const size_t g = (size_t)rowBase + tid;
        out[2 * g]     = w0;
        out[2 * g + 1] = w1;
        float* oi = out + 2 * (size_t)B_TOK;
        oi[2 * g]     = (float)i0;
        oi[2 * g + 1] = (float)i1;
    }
}

extern "C" void kernel_launch(void* const* d_in, const int* in_sizes, int n_in,
                              void* d_out, int out_size)
{
    const float* h    = (const float*)d_in[0];
    const float* w    = (const float*)d_in[1];
    const float* bias = (const float*)d_in[2];
    float* out        = (float*)d_out;

    const int smem_bytes = 16384 * sizeof(float);   // 64 KB
    cudaFuncSetAttribute(mome_gate2,
                         cudaFuncAttributeMaxDynamicSharedMemorySize, smem_bytes);
    mome_gate2<<<B_TOK / BM, NT, smem_bytes>>>(h, w, bias, out);
}

// round 4
// speedup vs baseline: 2.1464x; 1.0658x over previous
#include <cuda_runtime.h>
#include <cuda_bf16.h>
#include <cstdint>

#define DIMK   4096
#define NEXP   64
#define BTOK   16384
#define MTILE  128
#define KB     64            // fp32 k per chunk
#define NCHUNK (DIMK / KB)
#define NTHR   256
#define BUFSZ  49152          // A0(16K)+A1(16K)+B0(8K)+B1(8K)
#define BIAS_OFF 98304
#define CNT_OFF  98560
#define LIST_OFF 98576
#define SMEM_BYTES 99328
#define DELTA  1e-3f

// pre-split, pre-swizzled w tiles: [chunk][split][64e*64k bf16]
static __device__ __align__(16) unsigned short g_ws[NCHUNK][2][4096];

// ---------------- helpers ----------------
__device__ __forceinline__ unsigned smem_u32(const void* p) {
    return (unsigned)__cvta_generic_to_shared(p);
}
__device__ __forceinline__ void cpa16(unsigned dst, const void* src) {
    asm volatile("cp.async.cg.shared.global [%0], [%1], 16;" :: "r"(dst), "l"(src));
}
__device__ __forceinline__ unsigned packbf(float hi, float lo) {
    unsigned r;
    asm("cvt.rn.bf16x2.f32 %0, %1, %2;" : "=r"(r) : "f"(hi), "f"(lo));
    return r;
}
__device__ __forceinline__ void ldsm4(unsigned* r, unsigned a) {
    asm volatile("ldmatrix.sync.aligned.m8n8.x4.shared.b16 {%0,%1,%2,%3}, [%4];"
                 : "=r"(r[0]), "=r"(r[1]), "=r"(r[2]), "=r"(r[3]) : "r"(a));
}
#define MMA(d, a, b0v, b1v)                                                    \
    asm volatile(                                                              \
        "mma.sync.aligned.m16n8k16.row.col.f32.bf16.bf16.f32 "                 \
        "{%0,%1,%2,%3},{%4,%5,%6,%7},{%8,%9},{%0,%1,%2,%3};"                   \
        : "+f"((d)[0]), "+f"((d)[1]), "+f"((d)[2]), "+f"((d)[3])               \
        : "r"((a)[0]), "r"((a)[1]), "r"((a)[2]), "r"((a)[3]),                  \
          "r"(b0v), "r"(b1v))

// ---------------- w split precompute ----------------
__global__ void wsplit_kernel(const float* __restrict__ w) {
    const int idx = blockIdx.x * 256 + threadIdx.x;     // e*4096 + k
    const int e = idx >> 12, k = idx & 4095;
    const float x = w[idx];
    const unsigned short b0 = __bfloat16_as_ushort(__float2bfloat16(x));
    const float r = x - __uint_as_float((unsigned)b0 << 16);
    const unsigned short b1 = __bfloat16_as_ushort(__float2bfloat16(r));
    const int c = k >> 6, kk = k & 63;
    const unsigned off = ((unsigned)e << 7) + (((unsigned)kk * 2) ^ ((e & 7) << 4));
    g_ws[c][0][off >> 1] = b0;
    g_ws[c][1][off >> 1] = b1;
}

// ---------------- main ----------------
__global__ void __launch_bounds__(NTHR, 1)
mome_gate_mma(const float* __restrict__ h,
              const float* __restrict__ w,
              const float* __restrict__ bias,
              float* __restrict__ out)
{
    extern __shared__ char smc[];
    const unsigned smb = smem_u32(smc);
    const int tid  = threadIdx.x;
    const int lane = tid & 31;
    const int wid  = tid >> 5;
    const int wr   = wid >> 1;     // row block  (32 rows)
    const int we   = wid & 1;      // expert blk (32 experts)
    const size_t rowBase = (size_t)blockIdx.x * MTILE;

    if (tid == 0) *(int*)(smc + CNT_OFF) = 0;
    if (tid < NEXP) ((float*)(smc + BIAS_OFF))[tid] = bias[tid];

    // producer mapping
    const int row0 = tid >> 4;           // 0..15, +16*i
    const int f4   = tid & 15;
    const float* hg = h + (rowBase + row0) * DIMK + f4 * 4;

    // ldmatrix lane geometry (shared by A and B)
    const int mrow  = (lane & 7) + ((lane >> 3) & 1) * 8;  // 0..15
    const unsigned klane = ((unsigned)(lane >> 4)) * 16;   // 0 or 16 bytes
    const unsigned xorv  = ((unsigned)(lane & 7)) << 4;
    const unsigned arowoff = (unsigned)(wr * 32 + mrow) * 128;
    const unsigned browoff = (unsigned)(we * 32 + mrow) * 128;

    float acc[2][4][4];
#pragma unroll
    for (int m = 0; m < 2; m++)
#pragma unroll
        for (int j = 0; j < 4; j++)
#pragma unroll
            for (int q = 0; q < 4; q++) acc[m][j][q] = 0.f;

    float4 r[8];
    auto loadA = [&](int c) {
#pragma unroll
        for (int i = 0; i < 8; i++)
            r[i] = *(const float4*)(hg + (size_t)i * 16 * DIMK + (size_t)c * KB);
    };
    auto storeA = [&](int buf) {
        char* Ab0 = smc + buf * BUFSZ;
        char* Ab1 = Ab0 + 16384;
        const unsigned xr = (unsigned)((row0 & 7) << 4);
#pragma unroll
        for (int i = 0; i < 8; i++) {
            const unsigned off = (unsigned)(row0 + i * 16) * 128 + (((unsigned)f4 * 8) ^ xr);
            const float4 v = r[i];
            const unsigned p0 = packbf(v.y, v.x);
            const unsigned p1 = packbf(v.w, v.z);
            const float rx = v.x - __uint_as_float(p0 << 16);
            const float ry = v.y - __uint_as_float(p0 & 0xffff0000u);
            const float rz = v.z - __uint_as_float(p1 << 16);
            const float rw = v.w - __uint_as_float(p1 & 0xffff0000u);
            const unsigned q0 = packbf(ry, rx);
            const unsigned q1 = packbf(rw, rz);
            *(uint2*)(Ab0 + off) = make_uint2(p0, p1);
            *(uint2*)(Ab1 + off) = make_uint2(q0, q1);
        }
    };
    auto loadB = [&](int c, int buf) {
        const char* src = (const char*)g_ws[c];
        const unsigned dst = smb + buf * BUFSZ + 32768;
#pragma unroll
        for (int j = 0; j < 4; j++)
            cpa16(dst + j * 4096 + tid * 16, src + j * 4096 + tid * 16);
        asm volatile("cp.async.commit_group;" ::: "memory");
    };
    auto compute = [&](int buf) {
        const unsigned base = smb + buf * BUFSZ;
#pragma unroll
        for (int t = 0; t < 3; t++) {
            const int as = (t == 2) ? 1 : 0;
            const int bs = (t == 1) ? 1 : 0;
            const unsigned Ab = base + as * 16384 + arowoff;
            const unsigned Bb = base + 32768 + bs * 8192 + browoff;
#pragma unroll
            for (int kb = 0; kb < 4; kb++) {
                const unsigned ko = ((unsigned)kb * 32 + klane) ^ xorv;
                unsigned a0[4], a1[4], b0[4], b1[4];
                ldsm4(a0, Ab + ko);
                ldsm4(a1, Ab + 2048 + ko);
                ldsm4(b0, Bb + ko);
                ldsm4(b1, Bb + 2048 + ko);
                MMA(acc[0][0], a0, b0[0], b0[2]);
                MMA(acc[0][1], a0, b0[1], b0[3]);
                MMA(acc[0][2], a0, b1[0], b1[2]);
                MMA(acc[0][3], a0, b1[1], b1[3]);
                MMA(acc[1][0], a1, b0[0], b0[2]);
                MMA(acc[1][1], a1, b0[1], b0[3]);
                MMA(acc[1][2], a1, b1[0], b1[2]);
                MMA(acc[1][3], a1, b1[1], b1[3]);
            }
        }
    };

    // prologue: chunk 0
    loadA(0);
    storeA(0);
    loadB(0, 0);
    asm volatile("cp.async.wait_group 0;" ::: "memory");

    for (int c = 0; c < NCHUNK; c++) {
        __syncthreads();
        const int buf = c & 1;
        if (c + 1 < NCHUNK) { loadB(c + 1, buf ^ 1); loadA(c + 1); }
        compute(buf);
        if (c + 1 < NCHUNK) {
            storeA(buf ^ 1);
            asm volatile("cp.async.wait_group 0;" ::: "memory");
        }
    }
    __syncthreads();

    // ---- dump logits to smem (reuse buffer0): Ls[128][68] ----
    float* Ls = (float*)smc;
    {
        const int rin = lane >> 2;
        const int cin = (lane & 3) * 2;
#pragma unroll
        for (int m = 0; m < 2; m++) {
            const int r0i = wr * 32 + m * 16 + rin;
#pragma unroll
            for (int j = 0; j < 4; j++) {
                const int n = we * 32 + j * 8 + cin;
                Ls[r0i * 68 + n]           = acc[m][j][0];
                Ls[r0i * 68 + n + 1]       = acc[m][j][1];
                Ls[(r0i + 8) * 68 + n]     = acc[m][j][2];
                Ls[(r0i + 8) * 68 + n + 1] = acc[m][j][3];
            }
        }
    }
    __syncthreads();

    // ---- per-row top-3 scan, flag near-ties ----
    const float* bias_s = (const float*)(smc + BIAS_OFF);
    if (tid < MTILE) {
        const float* lrow = &Ls[tid * 68];
        float v0 = -1e30f, v1 = -1e30f, v2 = -1e30f;
        int i0 = 0, i1 = 0;
#pragma unroll 8
        for (int e = 0; e < NEXP; e++) {
            const float v = lrow[e] + bias_s[e];
            if (v > v0)      { v2 = v1; v1 = v0; i1 = i0; v0 = v; i0 = e; }
            else if (v > v1) { v2 = v1; v1 = v; i1 = e; }
            else if (v > v2) { v2 = v; }
        }
        if ((v0 - v1 < DELTA) || (v1 - v2 < DELTA)) {
            const int slot = atomicAdd((int*)(smc + CNT_OFF), 1);
            ((int*)(smc + LIST_OFF))[slot] = tid;
        } else {
            const float t  = __expf(v1 - v0);
            const float w0 = 1.0f / (1.0f + t);
            const size_t g = rowBase + tid;
            out[2 * g]     = w0;
            out[2 * g + 1] = 1.0f - w0;
            float* oi = out + 2 * (size_t)BTOK;
            oi[2 * g]     = (float)i0;
            oi[2 * g + 1] = (float)i1;
        }
    }
    __syncthreads();

    // ---- exact fp32 rescue for flagged rows (rare: <1/CTA expected) ----
    const int nf = *(const int*)(smc + CNT_OFF);
    float* P  = (float*)smc;            // [4][64] partials (Ls dead now)
    float* Lr = (float*)(smc + 4096);   // [64] refined logits
    for (int f = 0; f < nf; f++) {
        const int rrow = ((const int*)(smc + LIST_OFF))[f];
        const float* hr = h + (rowBase + rrow) * DIMK;
        const int e = tid & 63, q = tid >> 6;
        const float* wp = w + (size_t)e * DIMK + q * 1024;
        const float* hp = hr + q * 1024;
        float s = 0.f;
        for (int k = 0; k < 1024; k += 4) {
            const float4 hv = *(const float4*)(hp + k);
            const float4 wv = *(const float4*)(wp + k);
            s += hv.x * wv.x + hv.y * wv.y + hv.z * wv.z + hv.w * wv.w;
        }
        P[q * 64 + e] = s;
        __syncthreads();
        if (tid < NEXP)
            Lr[tid] = P[tid] + P[64 + tid] + P[128 + tid] + P[192 + tid] + bias_s[tid];
        __syncthreads();
        if (tid == 0) {
            float v0 = -1e30f, v1 = -1e30f;
            int i0 = 0, i1 = 0;
            for (int e2 = 0; e2 < NEXP; e2++) {
                const float v = Lr[e2];
                if (v > v0)      { v1 = v0; i1 = i0; v0 = v; i0 = e2; }
                else if (v > v1) { v1 = v; i1 = e2; }
            }
            const float t  = __expf(v1 - v0);
            const float w0 = 1.0f / (1.0f + t);
            const size_t g = rowBase + rrow;
            out[2 * g]     = w0;
            out[2 * g + 1] = 1.0f - w0;
            float* oi = out + 2 * (size_t)BTOK;
            oi[2 * g]     = (float)i0;
            oi[2 * g + 1] = (float)i1;
        }
        __syncthreads();
    }
}

extern "C" void kernel_launch(void* const* d_in, const int* in_sizes, int n_in,
                              void* d_out, int out_size)
{
    const float* h    = (const float*)d_in[0];
    const float* w    = (const float*)d_in[1];
    const float* bias = (const float*)d_in[2];
    float* out        = (float*)d_out;

    wsplit_kernel<<<(NEXP * DIMK) / 256, 256>>>(w);

    cudaFuncSetAttribute(mome_gate_mma,
                         cudaFuncAttributeMaxDynamicSharedMemorySize, SMEM_BYTES);
    mome_gate_mma<<<BTOK / MTILE, NTHR, SMEM_BYTES>>>(h, w, bias, out);
}